// round 13
// baseline (speedup 1.0000x reference)
#include <cuda_runtime.h>
#include <stdint.h>

#define D_    64
#define H_    32
#define W_    32
#define CIN_  128
#define COUT_ 128
#define NPIX  (D_*H_*W_)     // 65536
#define KOFF  1152
#define ROWS  2
#define PACKW_BLOCKS (D_*9*2)     // 1152

// -------- scratch (no allocations allowed) --------
__device__ uint4 g_wb[D_*9*COUT_];      // packed w bits per (d,tap,cout)
__device__ int   g_mode;                // 0=uint8, 1=32-bit(int32/f32), 3=bf16

// carry-save adder primitives: any 3-input boolean = one LOP3
__device__ __forceinline__ uint32_t xor3(uint32_t a, uint32_t b, uint32_t c){
    uint32_t r;
    asm("lop3.b32 %0, %1, %2, %3, 0x96;" : "=r"(r) : "r"(a), "r"(b), "r"(c));
    return r;
}
__device__ __forceinline__ uint32_t maj3(uint32_t a, uint32_t b, uint32_t c){
    uint32_t r;
    asm("lop3.b32 %0, %1, %2, %3, 0xE8;" : "=r"(r) : "r"(a), "r"(b), "r"(c));
    return r;
}

// Bit mapping (MUST match between x and w): word q (0..3), bit l (0..31)
// <-> channel 4*l + q.  XOR+popc is invariant under this fixed permutation.

// Kernel 1: pack w (one thread per (cout, word q); coalesced reads) and
// dtype-probe x (block 0, warp 0 -> g_mode).
__global__ __launch_bounds__(256)
void pack_kernel(const uint8_t* __restrict__ x, const float* __restrict__ w){
    int tid = threadIdx.x;
    if (blockIdx.x == 0 && tid < 32){
        const uint4* p4 = reinterpret_cast<const uint4*>(x);
        int gt1 = 0, nz = 0, bf = 0;
        for (int i = tid; i < 256; i += 32){
            uint4 a = p4[i];
            uint32_t r[4] = {a.x, a.y, a.z, a.w};
            #pragma unroll
            for (int e = 0; e < 4; e++){
                uint32_t v = r[e];
                if (v & 0xFEFEFEFEu)            gt1 = 1;  // any byte >1
                if (v & 0xFFFFFF00u)            nz  = 1;  // nonzero off word-pos
                if (((v >> 8) & 0xFFu) == 0x3F) bf  = 1;  // bf16 signature
            }
        }
        gt1 = __reduce_or_sync(0xFFFFFFFFu, gt1);
        nz  = __reduce_or_sync(0xFFFFFFFFu, nz);
        bf  = __reduce_or_sync(0xFFFFFFFFu, bf);
        if (tid == 0) g_mode = (!gt1) ? (nz ? 0 : 1) : (bf ? 3 : 1);
    }
    // ---- pack w: word q, bit l = channel 4l+q ----
    int b  = blockIdx.x;                         // (dt, q-half)
    int dt = b >> 1;                             // d*9 + tap
    int co = tid & 127;                          // lane-consecutive couts
    int q  = ((b & 1) << 1) + (tid >> 7);        // 0..3
    const float* wp = w + (size_t)dt * (CIN_ * COUT_);
    uint32_t v = 0;
    #pragma unroll
    for (int l = 0; l < 32; l++)
        v |= (wp[(size_t)(4*l + q) * COUT_ + co] != 0.0f ? 1u : 0u) << l;
    reinterpret_cast<uint32_t*>(g_wb)[(dt * COUT_ + co) * 4 + q] = v;
}

// Conv: XOR identity + CSA tree. Each block packs its own x tile via
// warp-cooperative ballot (coalesced 512B reads per pixel, bit l = ch 4l+q).
// out = K - 2*sum_{36} popc(x^w); 36 POPC -> 7 POPC via LOP3 CSAs.
// ROWS=2 -> 1024 CTAs (~99% SM balance), 128 threads (1 per cout).
__global__ __launch_bounds__(128)
void conv_kernel(const uint8_t* __restrict__ x, float* __restrict__ out){
    __shared__ uint4 xs[ROWS + 2][W_ + 2];
    int tid  = threadIdx.x;        // 0..127
    int co   = tid;
    int lane = tid & 31, warp = tid >> 5;
    int d    = blockIdx.y;
    int r0   = blockIdx.x * ROWS;
    int mode = g_mode;

    // ---- warp-ballot tile pack with zero halo ----
    for (int e = warp; e < (ROWS + 2) * (W_ + 2); e += 4){
        int rr = e / (W_ + 2), cc = e % (W_ + 2);
        int hh = r0 - 1 + rr, ww = cc - 1;
        if ((unsigned)hh < H_ && (unsigned)ww < W_){
            size_t pix = (size_t)(d * H_ + hh) * W_ + ww;
            uint32_t b0, b1, b2, b3;
            if (mode == 1){            // 32-bit 0/1 elems (int32/float32)
                uint4 a = reinterpret_cast<const uint4*>(x)[pix * 32 + lane];
                b0 = __ballot_sync(0xFFFFFFFFu, a.x != 0u);
                b1 = __ballot_sync(0xFFFFFFFFu, a.y != 0u);
                b2 = __ballot_sync(0xFFFFFFFFu, a.z != 0u);
                b3 = __ballot_sync(0xFFFFFFFFu, a.w != 0u);
            } else if (mode == 0){     // uint8 bool: 4 bytes per lane
                uint32_t a = reinterpret_cast<const uint32_t*>(x)[pix * 32 + lane];
                b0 = __ballot_sync(0xFFFFFFFFu, (a & 0x000000FFu) != 0u);
                b1 = __ballot_sync(0xFFFFFFFFu, (a & 0x0000FF00u) != 0u);
                b2 = __ballot_sync(0xFFFFFFFFu, (a & 0x00FF0000u) != 0u);
                b3 = __ballot_sync(0xFFFFFFFFu, (a & 0xFF000000u) != 0u);
            } else {                   // bf16: 4 halfwords per lane
                uint2 a = reinterpret_cast<const uint2*>(x)[pix * 32 + lane];
                b0 = __ballot_sync(0xFFFFFFFFu, (a.x & 0x0000FFFFu) != 0u);
                b1 = __ballot_sync(0xFFFFFFFFu, (a.x & 0xFFFF0000u) != 0u);
                b2 = __ballot_sync(0xFFFFFFFFu, (a.y & 0x0000FFFFu) != 0u);
                b3 = __ballot_sync(0xFFFFFFFFu, (a.y & 0xFFFF0000u) != 0u);
            }
            if (lane == 0) xs[rr][cc] = make_uint4(b0, b1, b2, b3);
        } else {
            if (lane == 0) xs[rr][cc] = make_uint4(0u, 0u, 0u, 0u);
        }
    }

    uint32_t wr[9][4];
    #pragma unroll
    for (int t = 0; t < 9; t++){
        uint4 v = g_wb[(d * 9 + t) * COUT_ + co];
        wr[t][0] = v.x; wr[t][1] = v.y; wr[t][2] = v.z; wr[t][3] = v.w;
    }
    __syncthreads();

    float* outp = out + ((size_t)(d * H_ + r0) * W_) * COUT_ + co;
    #pragma unroll 2
    for (int p = 0; p < ROWS * W_; p++){
        int pr = p >> 5, pc = p & 31;

        uint32_t S[4], C1[4], S2[4], C2[4];
        #pragma unroll
        for (int k = 0; k < 4; k++){
            uint32_t v[9];
            #pragma unroll
            for (int t = 0; t < 9; t++){
                const uint32_t* xw = reinterpret_cast<const uint32_t*>(&xs[pr + t / 3][pc + t % 3]);
                v[t] = xw[k] ^ wr[t][k];
            }
            uint32_t sa = xor3(v[0], v[1], v[2]), ca = maj3(v[0], v[1], v[2]);
            uint32_t sb = xor3(v[3], v[4], v[5]), cb = maj3(v[3], v[4], v[5]);
            uint32_t sc = xor3(v[6], v[7], v[8]), cc = maj3(v[6], v[7], v[8]);
            S [k] = xor3(sa, sb, sc);  C1[k] = maj3(sa, sb, sc);   // w1, w2
            S2[k] = xor3(ca, cb, cc);  C2[k] = maj3(ca, cb, cc);   // w2, w4
        }
        // w1 pool: S[0..3]
        uint32_t sA = xor3(S[0], S[1], S[2]), cA = maj3(S[0], S[1], S[2]);
        int P1 = __popc(sA) + __popc(S[3]);
        // w2 pool: C1[0..3], S2[0..3], cA  (9 words)
        uint32_t t0 = xor3(C1[0], C1[1], C1[2]), u0 = maj3(C1[0], C1[1], C1[2]);
        uint32_t t1 = xor3(C1[3], S2[0], S2[1]), u1 = maj3(C1[3], S2[0], S2[1]);
        uint32_t t2 = xor3(S2[2], S2[3], cA),    u2 = maj3(S2[2], S2[3], cA);
        uint32_t t3 = xor3(t0, t1, t2),          u3 = maj3(t0, t1, t2);
        int P2 = __popc(t3);
        // w4 pool: C2[0..3], u0..u3  (8 words)
        uint32_t q0 = xor3(C2[0], C2[1], C2[2]), r0w = maj3(C2[0], C2[1], C2[2]);
        uint32_t q1 = xor3(C2[3], u0, u1),       r1w = maj3(C2[3], u0, u1);
        uint32_t q2 = xor3(u2, u3, q0),          r2w = maj3(u2, u3, q0);
        int P4 = __popc(q1) + __popc(q2);
        // w8 pool: r0w, r1w, r2w
        uint32_t s8 = xor3(r0w, r1w, r2w), c16 = maj3(r0w, r1w, r2w);
        int P8  = __popc(s8);
        int P16 = __popc(c16);

        int acc = P1 + 2*P2 + 4*P4 + 8*P8 + 16*P16;
        outp[(size_t)p * COUT_] = (float)(KOFF - 2 * acc);
    }
}

extern "C" void kernel_launch(void* const* d_in, const int* in_sizes, int n_in,
                              void* d_out, int out_size){
    const void* in0 = d_in[0];
    const void* in1 = d_in[1];
    // defensive: identify x vs w (9437184 elems) by size
    if (in_sizes[0] == D_*9*CIN_*COUT_) { const void* t = in0; in0 = in1; in1 = t; }
    const uint8_t* x = (const uint8_t*)in0;
    const float*   w = (const float*)in1;
    float* out = (float*)d_out;

    pack_kernel<<<PACKW_BLOCKS, 256>>>(x, w);
    conv_kernel<<<dim3(H_ / ROWS, D_), 128>>>(x, out);
}

// round 14
// speedup vs baseline: 1.2532x; 1.2532x over previous
#include <cuda_runtime.h>
#include <stdint.h>

#define D_    64
#define H_    32
#define W_    32
#define CIN_  128
#define COUT_ 128
#define NPIX  (D_*H_*W_)     // 65536
#define KOFF  1152
#define ROWS  2
#define PX_PER_BLK 64
#define PACKX_BLOCKS (NPIX/PX_PER_BLK)  // 1024
#define PACKW_BLOCKS (D_*9*2)           // 1152
#define STRIDE_W 132                    // padded words per staged pixel

// -------- scratch (no allocations allowed) --------
__device__ uint4 g_xb[NPIX];            // packed x bits: 128 bits / pixel
__device__ uint4 g_wb[D_*9*COUT_];      // packed w bits per (d,tap,cout)

// bytes of v are 0/1: returns b0 | b1<<1 | b2<<2 | b3<<3
__device__ __forceinline__ uint32_t nib(uint32_t v){
    return (v | (v >> 7) | (v >> 14) | (v >> 21)) & 0xFu;
}

// carry-save adder primitives: any 3-input boolean = one LOP3
__device__ __forceinline__ uint32_t xor3(uint32_t a, uint32_t b, uint32_t c){
    uint32_t r;
    asm("lop3.b32 %0, %1, %2, %3, 0x96;" : "=r"(r) : "r"(a), "r"(b), "r"(c));
    return r;
}
__device__ __forceinline__ uint32_t maj3(uint32_t a, uint32_t b, uint32_t c){
    uint32_t r;
    asm("lop3.b32 %0, %1, %2, %3, 0xE8;" : "=r"(r) : "r"(a), "r"(b), "r"(c));
    return r;
}

// Fused packing kernel.
// Blocks [0,1024): pack x — stage 64 pixels (32KB) in smem with coalesced
//   uint4 loads, then 256 threads each pack one (pixel, word).
// Blocks [1024,2176): pack w — one thread per (cout,chunk), coalesced.
__global__ __launch_bounds__(256)
void pack_kernel(const uint8_t* __restrict__ x, const float* __restrict__ w){
    __shared__ uint32_t stage[PX_PER_BLK * STRIDE_W];   // 33792 B
    __shared__ int mode_s;
    int tid = threadIdx.x;

    if (blockIdx.x < PACKX_BLOCKS){
        // ---- dtype probe (per-block; first 4KB hits L2) ----
        if (tid < 32){
            const uint4* p4 = reinterpret_cast<const uint4*>(x);
            int gt1 = 0, nz = 0, bf = 0;
            for (int i = tid; i < 256; i += 32){
                uint4 a = p4[i];
                uint32_t r[4] = {a.x, a.y, a.z, a.w};
                #pragma unroll
                for (int e = 0; e < 4; e++){
                    uint32_t v = r[e];
                    if (v & 0xFEFEFEFEu)            gt1 = 1;  // any byte >1
                    if (v & 0xFFFFFF00u)            nz  = 1;  // nonzero off word-pos
                    if (((v >> 8) & 0xFFu) == 0x3F) bf  = 1;  // bf16 signature
                }
            }
            gt1 = __reduce_or_sync(0xFFFFFFFFu, gt1);
            nz  = __reduce_or_sync(0xFFFFFFFFu, nz);
            bf  = __reduce_or_sync(0xFFFFFFFFu, bf);
            if (tid == 0) mode_s = (!gt1) ? (nz ? 0 : 1) : (bf ? 3 : 2);
        }
        __syncthreads();
        int mode = mode_s;                 // 0=uint8, 1=int32, 2=float32, 3=bf16
        int p0 = blockIdx.x * PX_PER_BLK;

        if (mode == 1 || mode == 2){
            // ---- staged path for 32-bit 0/1 elems (int32 / float32) ----
            const uint4* src = reinterpret_cast<const uint4*>(x) + (size_t)p0 * 32;
            #pragma unroll
            for (int it = 0; it < 8; it++){
                int gidx = it * 256 + tid;               // 0..2047
                int pix = gidx >> 5, j = gidx & 31;
                uint4 a = src[gidx];                     // coalesced
                *reinterpret_cast<uint4*>(&stage[pix * STRIDE_W + j * 4]) = a;
            }
            __syncthreads();
            int pix = tid & 63, k = tid >> 6;            // 64 px x 4 words
            const uint32_t* row = &stage[pix * STRIDE_W + k * 32];
            uint32_t v = 0;
            #pragma unroll
            for (int i = 0; i < 32; i++)
                v |= (row[i] ? 1u : 0u) << i;
            reinterpret_cast<uint32_t*>(g_xb)[(p0 + pix) * 4 + k] = v;
        } else if (mode == 0){             // uint8 bool (fallback, unprofiled)
            if (tid < PX_PER_BLK){
                int p = p0 + tid;
                const uint4* px = reinterpret_cast<const uint4*>(x) + (size_t)p * 8;
                uint32_t wd[4];
                #pragma unroll
                for (int k = 0; k < 4; k++){
                    uint4 a = px[2*k], b = px[2*k+1];
                    wd[k] = nib(a.x)        | (nib(a.y) << 4)  | (nib(a.z) << 8)  | (nib(a.w) << 12)
                          | (nib(b.x) << 16)| (nib(b.y) << 20) | (nib(b.z) << 24) | (nib(b.w) << 28);
                }
                g_xb[p] = make_uint4(wd[0], wd[1], wd[2], wd[3]);
            }
        } else {                           // bf16 0/1 (fallback, unprofiled)
            if (tid < PX_PER_BLK){
                int p = p0 + tid;
                const uint4* pb = reinterpret_cast<const uint4*>(x) + (size_t)p * 16;
                uint32_t wd[4];
                #pragma unroll
                for (int k = 0; k < 4; k++){
                    uint32_t v = 0;
                    #pragma unroll
                    for (int q = 0; q < 4; q++){
                        uint4 a = pb[k*4 + q];
                        uint32_t r[4] = {a.x, a.y, a.z, a.w};
                        #pragma unroll
                        for (int e = 0; e < 4; e++){
                            v |= ((r[e] & 0x0000FFFFu) ? 1u : 0u) << (q*8 + e*2 + 0);
                            v |= ((r[e] & 0xFFFF0000u) ? 1u : 0u) << (q*8 + e*2 + 1);
                        }
                    }
                    wd[k] = v;
                }
                g_xb[p] = make_uint4(wd[0], wd[1], wd[2], wd[3]);
            }
        }
    } else {
        // ---- pack w: transpose-free, coalesced across cout ----
        int b     = blockIdx.x - PACKX_BLOCKS;      // (dt, chunk-half)
        int dt    = b >> 1;                          // d*9 + tap
        int co    = tid & 127;                       // lane-consecutive couts
        int chunk = ((b & 1) << 1) + (tid >> 7);     // 0..3
        const float* wp = w + (size_t)dt * (CIN_ * COUT_) + (size_t)chunk * 32 * COUT_;
        uint32_t v = 0;
        #pragma unroll
        for (int ci = 0; ci < 32; ci++)
            v |= (wp[ci * COUT_ + co] != 0.0f ? 1u : 0u) << ci;
        reinterpret_cast<uint32_t*>(g_wb)[(dt * COUT_ + co) * 4 + chunk] = v;
    }
}

// Conv: XOR identity + CSA tree on pre-packed bits (proven R11 body).
// out = K - 2 * sum_{36 words} popc(x ^ w); 36 POPC -> 7 POPC via LOP3 CSAs.
// ROWS=2 -> 1024 CTAs for ~99% SM balance; 128 threads (1/cout).
__global__ __launch_bounds__(128)
void conv_kernel(float* __restrict__ out){
    __shared__ uint4 xs[ROWS + 2][W_ + 2];
    int co = threadIdx.x;          // 0..127
    int d  = blockIdx.y;
    int r0 = blockIdx.x * ROWS;

    // x tile with zero halo (pre-packed)
    for (int i = co; i < (ROWS + 2) * (W_ + 2); i += 128){
        int rr = i / (W_ + 2), cc = i % (W_ + 2);
        int hh = r0 - 1 + rr, ww = cc - 1;
        uint4 v = make_uint4(0u, 0u, 0u, 0u);
        if ((unsigned)hh < H_ && (unsigned)ww < W_)
            v = g_xb[(d * H_ + hh) * W_ + ww];
        xs[rr][cc] = v;
    }

    uint32_t wr[9][4];
    #pragma unroll
    for (int t = 0; t < 9; t++){
        uint4 v = g_wb[(d * 9 + t) * COUT_ + co];
        wr[t][0] = v.x; wr[t][1] = v.y; wr[t][2] = v.z; wr[t][3] = v.w;
    }
    __syncthreads();

    float* outp = out + ((size_t)(d * H_ + r0) * W_) * COUT_ + co;
    #pragma unroll 2
    for (int p = 0; p < ROWS * W_; p++){
        int pr = p >> 5, pc = p & 31;

        uint32_t S[4], C1[4], S2[4], C2[4];
        #pragma unroll
        for (int k = 0; k < 4; k++){
            uint32_t v[9];
            #pragma unroll
            for (int t = 0; t < 9; t++){
                const uint32_t* xw = reinterpret_cast<const uint32_t*>(&xs[pr + t / 3][pc + t % 3]);
                v[t] = xw[k] ^ wr[t][k];
            }
            uint32_t sa = xor3(v[0], v[1], v[2]), ca = maj3(v[0], v[1], v[2]);
            uint32_t sb = xor3(v[3], v[4], v[5]), cb = maj3(v[3], v[4], v[5]);
            uint32_t sc = xor3(v[6], v[7], v[8]), cc = maj3(v[6], v[7], v[8]);
            S [k] = xor3(sa, sb, sc);  C1[k] = maj3(sa, sb, sc);   // w1, w2
            S2[k] = xor3(ca, cb, cc);  C2[k] = maj3(ca, cb, cc);   // w2, w4
        }
        // w1 pool: S[0..3]
        uint32_t sA = xor3(S[0], S[1], S[2]), cA = maj3(S[0], S[1], S[2]);
        int P1 = __popc(sA) + __popc(S[3]);
        // w2 pool: C1[0..3], S2[0..3], cA  (9 words)
        uint32_t t0 = xor3(C1[0], C1[1], C1[2]), u0 = maj3(C1[0], C1[1], C1[2]);
        uint32_t t1 = xor3(C1[3], S2[0], S2[1]), u1 = maj3(C1[3], S2[0], S2[1]);
        uint32_t t2 = xor3(S2[2], S2[3], cA),    u2 = maj3(S2[2], S2[3], cA);
        uint32_t t3 = xor3(t0, t1, t2),          u3 = maj3(t0, t1, t2);
        int P2 = __popc(t3);
        // w4 pool: C2[0..3], u0..u3  (8 words)
        uint32_t q0 = xor3(C2[0], C2[1], C2[2]), r0w = maj3(C2[0], C2[1], C2[2]);
        uint32_t q1 = xor3(C2[3], u0, u1),       r1w = maj3(C2[3], u0, u1);
        uint32_t q2 = xor3(u2, u3, q0),          r2w = maj3(u2, u3, q0);
        int P4 = __popc(q1) + __popc(q2);
        // w8 pool: r0w, r1w, r2w
        uint32_t s8 = xor3(r0w, r1w, r2w), c16 = maj3(r0w, r1w, r2w);
        int P8  = __popc(s8);
        int P16 = __popc(c16);

        int acc = P1 + 2*P2 + 4*P4 + 8*P8 + 16*P16;
        outp[(size_t)p * COUT_] = (float)(KOFF - 2 * acc);
    }
}

extern "C" void kernel_launch(void* const* d_in, const int* in_sizes, int n_in,
                              void* d_out, int out_size){
    const void* in0 = d_in[0];
    const void* in1 = d_in[1];
    // defensive: identify x vs w (9437184 elems) by size
    if (in_sizes[0] == D_*9*CIN_*COUT_) { const void* t = in0; in0 = in1; in1 = t; }
    const uint8_t* x = (const uint8_t*)in0;
    const float*   w = (const float*)in1;
    float* out = (float*)d_out;

    pack_kernel<<<PACKX_BLOCKS + PACKW_BLOCKS, 256>>>(x, w);
    conv_kernel<<<dim3(H_ / ROWS, D_), 128>>>(out);
}